// round 2
// baseline (speedup 1.0000x reference)
#include <cuda_runtime.h>

// Problem constants (match reference setup_inputs)
#define C_CH   256
#define K_KERN 4
#define HID    64      // C / RED
#define H_DIM  64
#define W_DIM  64
#define HW     4096    // H*W
#define B_MAX  32

// Scratch (no allocation allowed in kernel_launch)
__device__ float g_gap[B_MAX * C_CH];   // [B, C] global average pool
__device__ float g_attn[B_MAX * K_KERN];

// ---------------------------------------------------------------------------
// Kernel 1: global average pool per (b,c) plane. One block per plane.
// ---------------------------------------------------------------------------
__global__ void __launch_bounds__(256) gap_kernel(const float* __restrict__ x) {
    const int bc = blockIdx.x;
    const float4* __restrict__ p = (const float4*)(x + (size_t)bc * HW);
    float s = 0.f;
#pragma unroll
    for (int i = 0; i < 4; i++) {
        float4 v = p[threadIdx.x + i * 256];
        s += (v.x + v.y) + (v.z + v.w);
    }
#pragma unroll
    for (int o = 16; o > 0; o >>= 1) s += __shfl_down_sync(0xffffffffu, s, o);
    __shared__ float ws[8];
    const int lane = threadIdx.x & 31, w = threadIdx.x >> 5;
    if (lane == 0) ws[w] = s;
    __syncthreads();
    if (threadIdx.x == 0) {
        float t = 0.f;
#pragma unroll
        for (int i = 0; i < 8; i++) t += ws[i];
        g_gap[bc] = t * (1.0f / (float)HW);
    }
}

// ---------------------------------------------------------------------------
// Kernel 2: fc1 -> relu -> fc2 -> softmax over K. One block per batch.
// ---------------------------------------------------------------------------
__global__ void __launch_bounds__(256) attn_kernel(const float* __restrict__ fc1_w,
                                                   const float* __restrict__ fc1_b,
                                                   const float* __restrict__ fc2_w,
                                                   const float* __restrict__ fc2_b) {
    const int b = blockIdx.x;
    __shared__ float g[C_CH];
    __shared__ float h[HID];
    __shared__ float lg[K_KERN];

    g[threadIdx.x] = g_gap[b * C_CH + threadIdx.x];
    __syncthreads();

    if (threadIdx.x < HID) {
        const float* __restrict__ wr = fc1_w + threadIdx.x * C_CH;
        float acc = fc1_b[threadIdx.x];
#pragma unroll 8
        for (int c = 0; c < C_CH; c++) acc = fmaf(g[c], wr[c], acc);
        h[threadIdx.x] = fmaxf(acc, 0.f);
    }
    __syncthreads();

    if (threadIdx.x < K_KERN) {
        const float* __restrict__ wr = fc2_w + threadIdx.x * HID;
        float acc = fc2_b[threadIdx.x];
#pragma unroll 8
        for (int j = 0; j < HID; j++) acc = fmaf(h[j], wr[j], acc);
        lg[threadIdx.x] = acc;
    }
    __syncthreads();

    if (threadIdx.x == 0) {
        float m = lg[0];
#pragma unroll
        for (int k = 1; k < K_KERN; k++) m = fmaxf(m, lg[k]);
        float e[K_KERN], s = 0.f;
#pragma unroll
        for (int k = 0; k < K_KERN; k++) { e[k] = expf(lg[k] - m); s += e[k]; }
        const float inv = 1.0f / s;
#pragma unroll
        for (int k = 0; k < K_KERN; k++) g_attn[b * K_KERN + k] = e[k] * inv;
    }
}

// ---------------------------------------------------------------------------
// Kernel 3: depthwise 3x3 with per-(b,c) effective filter
//           w_eff = sum_k attn[b,k] * conv_w[k,c].  One block per (b,c) plane.
// Shared tile 66x66 (stride 68) with zero halo; 16 pixels per thread.
// ---------------------------------------------------------------------------
#define S_STRIDE 68
__global__ void __launch_bounds__(256) conv_kernel(const float* __restrict__ x,
                                                   const float* __restrict__ conv_w,
                                                   float* __restrict__ out) {
    const int bc = blockIdx.x;
    const int b = bc >> 8;     // / 256
    const int c = bc & 255;

    __shared__ float s[66 * S_STRIDE];

    // Effective 9-tap filter (uniform across block; broadcast loads)
    const float a0 = g_attn[b * 4 + 0];
    const float a1 = g_attn[b * 4 + 1];
    const float a2 = g_attn[b * 4 + 2];
    const float a3 = g_attn[b * 4 + 3];
    float w[9];
    const float* __restrict__ w0 = conv_w + (size_t)0 * C_CH * 9 + c * 9;
    const float* __restrict__ w1 = conv_w + (size_t)1 * C_CH * 9 + c * 9;
    const float* __restrict__ w2 = conv_w + (size_t)2 * C_CH * 9 + c * 9;
    const float* __restrict__ w3 = conv_w + (size_t)3 * C_CH * 9 + c * 9;
#pragma unroll
    for (int i = 0; i < 9; i++)
        w[i] = fmaf(a0, w0[i], fmaf(a1, w1[i], fmaf(a2, w2[i], a3 * w3[i])));

    // Zero halo (whole tile; cheap)
    for (int i = threadIdx.x; i < 66 * S_STRIDE; i += 256) s[i] = 0.f;
    __syncthreads();

    // Stage 64x64 plane into interior
    const float4* __restrict__ xp = (const float4*)(x + (size_t)bc * HW);
#pragma unroll
    for (int i = 0; i < 4; i++) {
        const int idx = threadIdx.x + i * 256;   // 0..1023 float4s
        const int row = idx >> 4;                // /16 float4 per row
        const int c4  = idx & 15;
        float4 v = xp[idx];
        float* d = &s[(row + 1) * S_STRIDE + 1 + c4 * 4];
        d[0] = v.x; d[1] = v.y; d[2] = v.z; d[3] = v.w;
    }
    __syncthreads();

    float* __restrict__ op = out + (size_t)bc * HW;
#pragma unroll
    for (int it = 0; it < 16; it++) {
        const int p = it * 256 + threadIdx.x;
        const int row = p >> 6, col = p & 63;
        const float* sp = &s[row * S_STRIDE + col];  // top-left of 3x3 window
        float acc;
        acc = sp[0] * w[0];
        acc = fmaf(sp[1],              w[1], acc);
        acc = fmaf(sp[2],              w[2], acc);
        acc = fmaf(sp[S_STRIDE + 0],   w[3], acc);
        acc = fmaf(sp[S_STRIDE + 1],   w[4], acc);
        acc = fmaf(sp[S_STRIDE + 2],   w[5], acc);
        acc = fmaf(sp[2*S_STRIDE + 0], w[6], acc);
        acc = fmaf(sp[2*S_STRIDE + 1], w[7], acc);
        acc = fmaf(sp[2*S_STRIDE + 2], w[8], acc);
        op[p] = acc;
    }
}

// ---------------------------------------------------------------------------
extern "C" void kernel_launch(void* const* d_in, const int* in_sizes, int n_in,
                              void* d_out, int out_size) {
    const float* x      = (const float*)d_in[0];
    const float* conv_w = (const float*)d_in[1];
    const float* fc1_w  = (const float*)d_in[2];
    const float* fc1_b  = (const float*)d_in[3];
    const float* fc2_w  = (const float*)d_in[4];
    const float* fc2_b  = (const float*)d_in[5];
    float* out = (float*)d_out;

    const int B = in_sizes[0] / (C_CH * HW);   // 32

    gap_kernel<<<B * C_CH, 256>>>(x);
    attn_kernel<<<B, 256>>>(fc1_w, fc1_b, fc2_w, fc2_b);
    conv_kernel<<<B * C_CH, 256>>>(x, conv_w, out);
}

// round 4
// speedup vs baseline: 1.3109x; 1.3109x over previous
#include <cuda_runtime.h>

#define C_CH   256
#define K_KERN 4
#define HID    64
#define HW     4096
#define B_MAX  32
#define S_STRIDE 68

__device__ float g_gap[B_MAX * C_CH];
__device__ float g_attn[B_MAX * K_KERN];

// ---------------------------------------------------------------------------
// Kernel 1: global average pool per (b,c) plane. One block per plane.
// ---------------------------------------------------------------------------
__global__ void __launch_bounds__(256) gap_kernel(const float* __restrict__ x) {
    const int bc = blockIdx.x;
    const float4* __restrict__ p = (const float4*)(x + (size_t)bc * HW);
    float s = 0.f;
#pragma unroll
    for (int i = 0; i < 4; i++) {
        float4 v = p[threadIdx.x + i * 256];
        s += (v.x + v.y) + (v.z + v.w);
    }
#pragma unroll
    for (int o = 16; o > 0; o >>= 1) s += __shfl_down_sync(0xffffffffu, s, o);
    __shared__ float ws[8];
    const int lane = threadIdx.x & 31, w = threadIdx.x >> 5;
    if (lane == 0) ws[w] = s;
    __syncthreads();
    if (threadIdx.x == 0) {
        float t = 0.f;
#pragma unroll
        for (int i = 0; i < 8; i++) t += ws[i];
        g_gap[bc] = t * (1.0f / (float)HW);
    }
}

// ---------------------------------------------------------------------------
// Kernel 2: fc1 -> relu -> fc2 -> softmax. One block per batch.
// ---------------------------------------------------------------------------
__global__ void __launch_bounds__(256) attn_kernel(const float* __restrict__ fc1_w,
                                                   const float* __restrict__ fc1_b,
                                                   const float* __restrict__ fc2_w,
                                                   const float* __restrict__ fc2_b) {
    const int b = blockIdx.x;
    __shared__ float g[C_CH];
    __shared__ float h[HID];
    __shared__ float lg[K_KERN];

    g[threadIdx.x] = g_gap[b * C_CH + threadIdx.x];
    __syncthreads();

    if (threadIdx.x < HID) {
        const float* __restrict__ wr = fc1_w + threadIdx.x * C_CH;
        float acc = fc1_b[threadIdx.x];
#pragma unroll 8
        for (int c = 0; c < C_CH; c++) acc = fmaf(g[c], wr[c], acc);
        h[threadIdx.x] = fmaxf(acc, 0.f);
    }
    __syncthreads();

    if (threadIdx.x < K_KERN) {
        const float* __restrict__ wr = fc2_w + threadIdx.x * HID;
        float acc = fc2_b[threadIdx.x];
#pragma unroll 8
        for (int j = 0; j < HID; j++) acc = fmaf(h[j], wr[j], acc);
        lg[threadIdx.x] = acc;
    }
    __syncthreads();

    if (threadIdx.x == 0) {
        float m = lg[0];
#pragma unroll
        for (int k = 1; k < K_KERN; k++) m = fmaxf(m, lg[k]);
        float e[K_KERN], s = 0.f;
#pragma unroll
        for (int k = 0; k < K_KERN; k++) { e[k] = expf(lg[k] - m); s += e[k]; }
        const float inv = 1.0f / s;
#pragma unroll
        for (int k = 0; k < K_KERN; k++) g_attn[b * K_KERN + k] = e[k] * inv;
    }
}

// ---------------------------------------------------------------------------
// Kernel 3: depthwise 3x3 with effective filter w_eff = sum_k attn[b,k]*w[k,c].
// One block per (b,c) plane, REVERSED block order for L2 reuse after gap.
// Each thread: 4-col x 4-row output tile, register sliding window,
// 3 LDS per input row (1x128b + 2x32b), float4 streaming stores.
// ---------------------------------------------------------------------------
__global__ void __launch_bounds__(256) conv_kernel(const float* __restrict__ x,
                                                   const float* __restrict__ conv_w,
                                                   float* __restrict__ out) {
    const int bc = gridDim.x - 1 - blockIdx.x;   // reverse: hit x tail in L2
    const int b = bc >> 8;
    const int c = bc & 255;

    __shared__ float s[66 * S_STRIDE];

    const float a0 = g_attn[b * 4 + 0];
    const float a1 = g_attn[b * 4 + 1];
    const float a2 = g_attn[b * 4 + 2];
    const float a3 = g_attn[b * 4 + 3];
    float w[9];
    const float* __restrict__ w0 = conv_w + (size_t)0 * C_CH * 9 + c * 9;
    const float* __restrict__ w1 = conv_w + (size_t)1 * C_CH * 9 + c * 9;
    const float* __restrict__ w2 = conv_w + (size_t)2 * C_CH * 9 + c * 9;
    const float* __restrict__ w3 = conv_w + (size_t)3 * C_CH * 9 + c * 9;
#pragma unroll
    for (int i = 0; i < 9; i++)
        w[i] = fmaf(a0, w0[i], fmaf(a1, w1[i], fmaf(a2, w2[i], a3 * w3[i])));

    // Zero only the halo: rows 0 & 65 (cols 0..65), cols 0 & 65 (rows 1..64).
    // 66+66+64+64 = 260 cells.
    for (int i = threadIdx.x; i < 260; i += 256) {
        int idx;
        if (i < 66)        idx = i;                              // row 0
        else if (i < 132)  idx = 65 * S_STRIDE + (i - 66);       // row 65
        else if (i < 196)  idx = (i - 132 + 1) * S_STRIDE;       // col 0
        else               idx = (i - 196 + 1) * S_STRIDE + 65;  // col 65
        s[idx] = 0.f;
    }

    // Stage 64x64 plane into interior (no sync needed before: disjoint cells)
    const float4* __restrict__ xp = (const float4*)(x + (size_t)bc * HW);
#pragma unroll
    for (int i = 0; i < 4; i++) {
        const int idx = threadIdx.x + i * 256;   // 0..1023 float4s
        const int row = idx >> 4;
        const int c4  = idx & 15;
        float4 v = xp[idx];
        float* d = &s[(row + 1) * S_STRIDE + 1 + c4 * 4];
        d[0] = v.x; d[1] = v.y; d[2] = v.z; d[3] = v.w;
    }
    __syncthreads();

    // Thread tile: 4 cols x 4 rows.
    const int tx = threadIdx.x & 15;       // col group
    const int ty = threadIdx.x >> 4;       // row group
    const int oc = tx * 4;                 // output col base
    const int orow = ty * 4;               // output row base

    // row buffer: 3 input rows x 6 cols (input cols oc-1 .. oc+4)
    // smem row r holds input row r-1; output row R uses smem rows R..R+2,
    // smem cols oc..oc+5.
    float rb[3][6];
#pragma unroll
    for (int r = 0; r < 3; r++) {
        const float* sp = &s[(orow + r) * S_STRIDE + oc];
        float4 v = *(const float4*)sp;
        rb[r][0] = v.x; rb[r][1] = v.y; rb[r][2] = v.z; rb[r][3] = v.w;
        rb[r][4] = sp[4]; rb[r][5] = sp[5];
    }

    float* __restrict__ op = out + (size_t)bc * HW;
#pragma unroll
    for (int rr = 0; rr < 4; rr++) {
        float4 o;
        float* ov = (float*)&o;
#pragma unroll
        for (int i = 0; i < 4; i++) {
            float acc;
            acc = rb[0][i] * w[0];
            acc = fmaf(rb[0][i + 1], w[1], acc);
            acc = fmaf(rb[0][i + 2], w[2], acc);
            acc = fmaf(rb[1][i],     w[3], acc);
            acc = fmaf(rb[1][i + 1], w[4], acc);
            acc = fmaf(rb[1][i + 2], w[5], acc);
            acc = fmaf(rb[2][i],     w[6], acc);
            acc = fmaf(rb[2][i + 1], w[7], acc);
            acc = fmaf(rb[2][i + 2], w[8], acc);
            ov[i] = acc;
        }
        __stcs((float4*)&op[(orow + rr) * 64 + oc], o);

        if (rr < 3) {
            // slide window down: next input row = smem row orow+rr+3
#pragma unroll
            for (int i = 0; i < 6; i++) { rb[0][i] = rb[1][i]; rb[1][i] = rb[2][i]; }
            const float* sp = &s[(orow + rr + 3) * S_STRIDE + oc];
            float4 v = *(const float4*)sp;
            rb[2][0] = v.x; rb[2][1] = v.y; rb[2][2] = v.z; rb[2][3] = v.w;
            rb[2][4] = sp[4]; rb[2][5] = sp[5];
        }
    }
}

// ---------------------------------------------------------------------------
extern "C" void kernel_launch(void* const* d_in, const int* in_sizes, int n_in,
                              void* d_out, int out_size) {
    const float* x      = (const float*)d_in[0];
    const float* conv_w = (const float*)d_in[1];
    const float* fc1_w  = (const float*)d_in[2];
    const float* fc1_b  = (const float*)d_in[3];
    const float* fc2_w  = (const float*)d_in[4];
    const float* fc2_b  = (const float*)d_in[5];
    float* out = (float*)d_out;

    const int B = in_sizes[0] / (C_CH * HW);   // 32

    gap_kernel<<<B * C_CH, 256>>>(x);
    attn_kernel<<<B, 256>>>(fc1_w, fc1_b, fc2_w, fc2_b);
    conv_kernel<<<B * C_CH, 256>>>(x, conv_w, out);
}

// round 5
// speedup vs baseline: 1.4317x; 1.0921x over previous
#include <cuda_runtime.h>

#define C_CH   256
#define K_KERN 4
#define HID    64
#define HW     4096
#define B_MAX  32

__device__ float g_gap[B_MAX * C_CH];
__device__ float g_attn[B_MAX * K_KERN];

// ---------------------------------------------------------------------------
// Kernel 1: global average pool per (b,c) plane. One block per plane.
// ---------------------------------------------------------------------------
__global__ void __launch_bounds__(256) gap_kernel(const float* __restrict__ x) {
    const int bc = blockIdx.x;
    const float4* __restrict__ p = (const float4*)(x + (size_t)bc * HW);
    float s = 0.f;
#pragma unroll
    for (int i = 0; i < 4; i++) {
        float4 v = p[threadIdx.x + i * 256];
        s += (v.x + v.y) + (v.z + v.w);
    }
#pragma unroll
    for (int o = 16; o > 0; o >>= 1) s += __shfl_down_sync(0xffffffffu, s, o);
    __shared__ float ws[8];
    const int lane = threadIdx.x & 31, w = threadIdx.x >> 5;
    if (lane == 0) ws[w] = s;
    __syncthreads();
    if (threadIdx.x == 0) {
        float t = 0.f;
#pragma unroll
        for (int i = 0; i < 8; i++) t += ws[i];
        g_gap[bc] = t * (1.0f / (float)HW);
    }
}

// ---------------------------------------------------------------------------
// Kernel 2: fc1 -> relu -> fc2 -> softmax. One block per batch.
// ---------------------------------------------------------------------------
__global__ void __launch_bounds__(256) attn_kernel(const float* __restrict__ fc1_w,
                                                   const float* __restrict__ fc1_b,
                                                   const float* __restrict__ fc2_w,
                                                   const float* __restrict__ fc2_b) {
    const int b = blockIdx.x;
    __shared__ float g[C_CH];
    __shared__ float h[HID];
    __shared__ float lg[K_KERN];

    g[threadIdx.x] = g_gap[b * C_CH + threadIdx.x];
    __syncthreads();

    if (threadIdx.x < HID) {
        const float* __restrict__ wr = fc1_w + threadIdx.x * C_CH;
        float acc = fc1_b[threadIdx.x];
#pragma unroll 8
        for (int c = 0; c < C_CH; c++) acc = fmaf(g[c], wr[c], acc);
        h[threadIdx.x] = fmaxf(acc, 0.f);
    }
    __syncthreads();

    if (threadIdx.x < K_KERN) {
        const float* __restrict__ wr = fc2_w + threadIdx.x * HID;
        float acc = fc2_b[threadIdx.x];
#pragma unroll 8
        for (int j = 0; j < HID; j++) acc = fmaf(h[j], wr[j], acc);
        lg[threadIdx.x] = acc;
    }
    __syncthreads();

    if (threadIdx.x == 0) {
        float m = lg[0];
#pragma unroll
        for (int k = 1; k < K_KERN; k++) m = fmaxf(m, lg[k]);
        float e[K_KERN], s = 0.f;
#pragma unroll
        for (int k = 0; k < K_KERN; k++) { e[k] = expf(lg[k] - m); s += e[k]; }
        const float inv = 1.0f / s;
#pragma unroll
        for (int k = 0; k < K_KERN; k++) g_attn[b * K_KERN + k] = e[k] * inv;
    }
}

// ---------------------------------------------------------------------------
// Kernel 3: depthwise 3x3, effective filter w_eff = sum_k attn[b,k]*w[k,c].
// NO shared memory, NO syncthreads. 16 lanes span a 64-wide row (float4/lane);
// horizontal halo comes from width-16 warp shuffles (sub 0/15 -> zero pad).
// Each half-warp streams an 8-row strip with a 3-row register window.
// Block = 256 threads = 16 half-warps = 2 planes (8 strips each).
// Reversed plane order -> consume x tail-first out of L2 left by gap_kernel.
// ---------------------------------------------------------------------------
__device__ __forceinline__ void load_row6(const float4* __restrict__ xp,
                                          int row, int sub, float* d) {
    float4 v;
    if ((unsigned)row < 64u) v = __ldg(&xp[row * 16 + sub]);
    else                     v = make_float4(0.f, 0.f, 0.f, 0.f);
    float l = __shfl_up_sync(0xffffffffu, v.w, 1, 16);
    float r = __shfl_down_sync(0xffffffffu, v.x, 1, 16);
    if (sub == 0)  l = 0.f;   // image left pad
    if (sub == 15) r = 0.f;   // image right pad
    d[0] = l; d[1] = v.x; d[2] = v.y; d[3] = v.z; d[4] = v.w; d[5] = r;
}

__global__ void __launch_bounds__(256) conv_kernel(const float* __restrict__ x,
                                                   const float* __restrict__ conv_w,
                                                   float* __restrict__ out) {
    const int tid  = threadIdx.x;
    const int lane = tid & 31;
    const int warp = tid >> 5;
    const int sub  = lane & 15;              // column group (0..15)
    const int gs   = warp * 2 + (lane >> 4); // global strip 0..15
    const int plane_local = gs >> 3;         // 0 or 1
    const int strip = gs & 7;                // 0..7

    const int pair = gridDim.x - 1 - blockIdx.x;      // reversed order
    const int bc = pair * 2 + plane_local;
    const int b = bc >> 8;
    const int c = bc & 255;

    // Effective 9-tap filter
    const float a0 = g_attn[b * 4 + 0];
    const float a1 = g_attn[b * 4 + 1];
    const float a2 = g_attn[b * 4 + 2];
    const float a3 = g_attn[b * 4 + 3];
    float w[9];
    const float* __restrict__ w0 = conv_w + (size_t)0 * C_CH * 9 + c * 9;
    const float* __restrict__ w1 = conv_w + (size_t)1 * C_CH * 9 + c * 9;
    const float* __restrict__ w2 = conv_w + (size_t)2 * C_CH * 9 + c * 9;
    const float* __restrict__ w3 = conv_w + (size_t)3 * C_CH * 9 + c * 9;
#pragma unroll
    for (int i = 0; i < 9; i++)
        w[i] = fmaf(a0, __ldg(&w0[i]),
               fmaf(a1, __ldg(&w1[i]),
               fmaf(a2, __ldg(&w2[i]), a3 * __ldg(&w3[i]))));

    const float4* __restrict__ xp = (const float4*)(x + (size_t)bc * HW);
    float4* __restrict__ op = (float4*)(out + (size_t)bc * HW);

    const int rbase = strip * 8;

    float rb[3][6];
    load_row6(xp, rbase - 1, sub, rb[0]);
    load_row6(xp, rbase,     sub, rb[1]);

#pragma unroll
    for (int rr = 0; rr < 8; rr++) {
        const int i0 = rr % 3;            // top row buffer
        const int i1 = (rr + 1) % 3;      // mid
        const int i2 = (rr + 2) % 3;      // bot (to fill)
        load_row6(xp, rbase + rr + 1, sub, rb[i2]);

        float4 o;
        float* ov = (float*)&o;
#pragma unroll
        for (int i = 0; i < 4; i++) {
            float acc;
            acc = rb[i0][i]     * w[0];
            acc = fmaf(rb[i0][i + 1], w[1], acc);
            acc = fmaf(rb[i0][i + 2], w[2], acc);
            acc = fmaf(rb[i1][i],     w[3], acc);
            acc = fmaf(rb[i1][i + 1], w[4], acc);
            acc = fmaf(rb[i1][i + 2], w[5], acc);
            acc = fmaf(rb[i2][i],     w[6], acc);
            acc = fmaf(rb[i2][i + 1], w[7], acc);
            acc = fmaf(rb[i2][i + 2], w[8], acc);
            ov[i] = acc;
        }
        __stcs(&op[(rbase + rr) * 16 + sub], o);
    }
}

// ---------------------------------------------------------------------------
extern "C" void kernel_launch(void* const* d_in, const int* in_sizes, int n_in,
                              void* d_out, int out_size) {
    const float* x      = (const float*)d_in[0];
    const float* conv_w = (const float*)d_in[1];
    const float* fc1_w  = (const float*)d_in[2];
    const float* fc1_b  = (const float*)d_in[3];
    const float* fc2_w  = (const float*)d_in[4];
    const float* fc2_b  = (const float*)d_in[5];
    float* out = (float*)d_out;

    const int B = in_sizes[0] / (C_CH * HW);   // 32

    gap_kernel<<<B * C_CH, 256>>>(x);
    attn_kernel<<<B, 256>>>(fc1_w, fc1_b, fc2_w, fc2_b);
    conv_kernel<<<B * C_CH / 2, 256>>>(x, conv_w, out);
}